// round 4
// baseline (speedup 1.0000x reference)
#include <cuda_runtime.h>
#include <math.h>

#define NB  512
#define NN  32
#define DSA 64
#define DH  128
#define PITCH 36   // floats/row: 144B -> every row+64B offset stays 16B-aligned for LDS.128

typedef unsigned long long u64;

#define ABSM  0x7fffffff7fffffffULL

// ---------- f32x2 helpers ----------
__device__ __forceinline__ u64 f2_fma(u64 a, u64 b, u64 c) {
    u64 d; asm("fma.rn.f32x2 %0,%1,%2,%3;" : "=l"(d) : "l"(a), "l"(b), "l"(c)); return d;
}
__device__ __forceinline__ u64 f2_add(u64 a, u64 b) {
    u64 d; asm("add.rn.f32x2 %0,%1,%2;" : "=l"(d) : "l"(a), "l"(b)); return d;
}
__device__ __forceinline__ u64 f2_pack(float lo, float hi) {
    u64 d; asm("mov.b64 %0,{%1,%2};" : "=l"(d) : "f"(lo), "f"(hi)); return d;
}
__device__ __forceinline__ float2 f2_unpack(u64 a) {
    float2 r; asm("mov.b64 {%0,%1},%2;" : "=f"(r.x), "=f"(r.y) : "l"(a)); return r;
}

// Paired-k, pre-duplicated transposed weights:
//   g_Wp[((k>>1)*DH + h)*2 + (k&1)] = pack(W[h][k], W[h][k])
// -> one LDG.128 yields packed weights for two consecutive k.
__device__ u64 g_Wp_msg1[128 * DH];   // k<128
__device__ u64 g_Wp_msg2[256 * DH];   // k<256
__device__ u64 g_Wp_up1 [192 * DH];   // k<192
__device__ u64 g_Wp_up2 [192 * DH];

__global__ void prep_weights_kernel(const float* __restrict__ Wm1,
                                    const float* __restrict__ Wm2,
                                    const float* __restrict__ Wu1,
                                    const float* __restrict__ Wu2) {
    const int stride = gridDim.x * blockDim.x;
    const int t0 = blockIdx.x * blockDim.x + threadIdx.x;
    for (int i = t0; i < DH * 128; i += stride) {
        int h = i >> 7, k = i & 127;
        float w = Wm1[i];
        g_Wp_msg1[((k >> 1) * DH + h) * 2 + (k & 1)] = f2_pack(w, w);
    }
    for (int i = t0; i < DH * 256; i += stride) {
        int h = i >> 8, k = i & 255;
        float w = Wm2[i];
        g_Wp_msg2[((k >> 1) * DH + h) * 2 + (k & 1)] = f2_pack(w, w);
    }
    for (int i = t0; i < DH * 192; i += stride) {
        int h = i / 192, k = i % 192;
        int d = ((k >> 1) * DH + h) * 2 + (k & 1);
        float w1 = Wu1[i], w2 = Wu2[i];
        g_Wp_up1[d] = f2_pack(w1, w1);
        g_Wp_up2[d] = f2_pack(w2, w2);
    }
}

// acc[0..7] += row-pairs (16 floats at `row`) * w2 (broadcast packed weight)
__device__ __forceinline__ void row_fma(u64* acc, const float* row, u64 w2) {
    const ulonglong2* xr = reinterpret_cast<const ulonglong2*>(row);
    #pragma unroll
    for (int q = 0; q < 4; q++) {
        ulonglong2 p = xr[q];
        acc[2*q]   = f2_fma(p.x, w2, acc[2*q]);
        acc[2*q+1] = f2_fma(p.y, w2, acc[2*q+1]);
    }
}
// dual-accumulator variant (msg layers): loads the row once
__device__ __forceinline__ void row_fma2(u64* accA, u64* accB, const float* row,
                                         u64 wa, u64 wb) {
    const ulonglong2* xr = reinterpret_cast<const ulonglong2*>(row);
    #pragma unroll
    for (int q = 0; q < 4; q++) {
        ulonglong2 p = xr[q];
        accA[2*q]   = f2_fma(p.x, wa, accA[2*q]);
        accB[2*q]   = f2_fma(p.x, wb, accB[2*q]);
        accA[2*q+1] = f2_fma(p.y, wa, accA[2*q+1]);
        accB[2*q+1] = f2_fma(p.y, wb, accB[2*q+1]);
    }
}

__global__ void __launch_bounds__(256, 3)
msggraph_kernel(const float* __restrict__ x,
                const float* __restrict__ bm1,
                const float* __restrict__ bm2,
                const float* __restrict__ bu1,
                const float* __restrict__ bu2,
                const float* __restrict__ Wv,
                const float* __restrict__ bv,
                float* __restrict__ out)
{
    __shared__ __align__(16) float xsT[DSA * PITCH];   // [k][j]
    __shared__ __align__(16) float PT [DH  * PITCH];   // [k][i]: agg1 -> v1 -> agg2
    __shared__ u64   Aex[16 * DH];                     // A exchange: [j2][h]
    __shared__ float mx[DH];
    __shared__ float red[8];

    const int tid  = threadIdx.x;
    const int h    = tid & 127;       // output channel
    const int half = tid >> 7;        // j/i half: 0 -> 0..15, 1 -> 16..31
    const int b    = blockIdx.x;
    const int coff = half * 16;       // column offset into shared rows

    // Load x[b] ([j=32][k=64] row-major) into transposed xsT[k][j].
    const float* xb = x + b * (NN * DSA);
    #pragma unroll
    for (int it = 0; it < (NN * DSA) / 256; it++) {
        int idx = it * 256 + tid;
        int j = idx >> 6, k = idx & 63;
        xsT[k * PITCH + j] = xb[idx];
    }
    __syncthreads();

    u64 accA[8], accB[8];   // my 16 j's as 8 packed pairs
    u64 Aall[16];           // all 32 A's (after exchange)
    u64 vacc[8];

    // ---- macro: msg epilogue (A-exchange + agg + PT write) ----
    // agg[i] = 0.5*(SA + 32*B_i + sum_j |A_j+B_i|) - relu(A_i+B_i)
#define MSG_EPILOGUE()                                                          \
    {                                                                           \
        _Pragma("unroll")                                                       \
        for (int q = 0; q < 8; q++) Aex[(half * 8 + q) * DH + h] = accA[q];     \
        __syncthreads();                                                        \
        _Pragma("unroll")                                                       \
        for (int q = 0; q < 8; q++) {                                           \
            Aall[half * 8 + q] = accA[q];                                       \
            Aall[(1 - half) * 8 + q] = Aex[((1 - half) * 8 + q) * DH + h];      \
        }                                                                       \
        u64 sAp = Aall[0];                                                      \
        _Pragma("unroll")                                                       \
        for (int j2 = 1; j2 < 16; j2++) sAp = f2_add(sAp, Aall[j2]);            \
        float2 sAf = f2_unpack(sAp);                                            \
        float SA = sAf.x + sAf.y;                                               \
        _Pragma("unroll")                                                       \
        for (int q = 0; q < 8; q++) {                                           \
            float2 B2 = f2_unpack(accB[q]);                                     \
            u64 bx = f2_pack(B2.x, B2.x), by = f2_pack(B2.y, B2.y);             \
            u64 ax = 0, ay = 0;                                                 \
            _Pragma("unroll")                                                   \
            for (int j2 = 0; j2 < 16; j2++) {                                   \
                u64 A = Aall[j2];                                               \
                ax = f2_add(ax, f2_add(A, bx) & ABSM);                          \
                ay = f2_add(ay, f2_add(A, by) & ABSM);                          \
            }                                                                   \
            float2 axf = f2_unpack(ax), ayf = f2_unpack(ay);                    \
            float2 Ai = f2_unpack(Aall[half * 8 + q]);                          \
            float gx = 0.5f * (fmaf(32.f, B2.x, SA) + axf.x + axf.y)            \
                       - fmaxf(Ai.x + B2.x, 0.f);                               \
            float gy = 0.5f * (fmaf(32.f, B2.y, SA) + ayf.x + ayf.y)            \
                       - fmaxf(Ai.y + B2.y, 0.f);                               \
            *reinterpret_cast<u64*>(&PT[h * PITCH + coff + 2 * q]) =            \
                f2_pack(gx, gy);                                                \
        }                                                                       \
    }

    // ================= Layer 1: msg =================
    {
        #pragma unroll
        for (int q = 0; q < 8; q++) { accA[q] = 0; accB[q] = 0; }
        const u64* W = g_Wp_msg1 + h * 2;
        #pragma unroll 4
        for (int k2 = 0; k2 < 32; k2++) {
            ulonglong2 wl = *reinterpret_cast<const ulonglong2*>(W + k2 * (DH * 2));
            ulonglong2 wr = *reinterpret_cast<const ulonglong2*>(W + (32 + k2) * (DH * 2));
            const float* r0 = xsT + (2 * k2) * PITCH + coff;
            row_fma2(accA, accB, r0, wl.x, wr.x);
            row_fma2(accA, accB, r0 + PITCH, wl.y, wr.y);
        }
        float bm = bm1[h];
        u64 bmp = f2_pack(bm, bm);
        #pragma unroll
        for (int q = 0; q < 8; q++) accA[q] = f2_add(accA[q], bmp);
        MSG_EPILOGUE()
    }
    __syncthreads();

    // ================= Layer 1: update =================
    {
        #pragma unroll
        for (int q = 0; q < 8; q++) vacc[q] = 0;
        const u64* W = g_Wp_up1 + h * 2;
        #pragma unroll 4
        for (int k2 = 0; k2 < 32; k2++) {            // x part (k<64)
            ulonglong2 w = *reinterpret_cast<const ulonglong2*>(W + k2 * (DH * 2));
            const float* r0 = xsT + (2 * k2) * PITCH + coff;
            row_fma(vacc, r0, w.x);
            row_fma(vacc, r0 + PITCH, w.y);
        }
        #pragma unroll 4
        for (int k2 = 0; k2 < 64; k2++) {            // agg part (k<128)
            ulonglong2 w = *reinterpret_cast<const ulonglong2*>(W + (32 + k2) * (DH * 2));
            const float* r0 = PT + (2 * k2) * PITCH + coff;
            row_fma(vacc, r0, w.x);
            row_fma(vacc, r0 + PITCH, w.y);
        }
        float bu = bu1[h];
        u64 bup = f2_pack(bu, bu);
        __syncthreads();   // everyone done reading PT(agg1)
        #pragma unroll
        for (int q = 0; q < 8; q++) {
            float2 t = f2_unpack(f2_add(vacc[q], bup));
            *reinterpret_cast<u64*>(&PT[h * PITCH + coff + 2 * q]) =
                f2_pack(fmaxf(t.x, 0.f), fmaxf(t.y, 0.f));
        }
    }
    __syncthreads();

    // ================= Layer 2: msg =================
    {
        #pragma unroll
        for (int q = 0; q < 8; q++) { accA[q] = 0; accB[q] = 0; }
        const u64* W = g_Wp_msg2 + h * 2;
        #pragma unroll 4
        for (int k2 = 0; k2 < 64; k2++) {
            ulonglong2 wl = *reinterpret_cast<const ulonglong2*>(W + k2 * (DH * 2));
            ulonglong2 wr = *reinterpret_cast<const ulonglong2*>(W + (64 + k2) * (DH * 2));
            const float* r0 = PT + (2 * k2) * PITCH + coff;
            row_fma2(accA, accB, r0, wl.x, wr.x);
            row_fma2(accA, accB, r0 + PITCH, wl.y, wr.y);
        }
        float bm = bm2[h];
        u64 bmp = f2_pack(bm, bm);
        #pragma unroll
        for (int q = 0; q < 8; q++) accA[q] = f2_add(accA[q], bmp);
        // the exchange's __syncthreads also separates GEMM reads of PT(v1)
        // from the epilogue's PT(agg2) writes
        MSG_EPILOGUE()
    }
    __syncthreads();

    // ================= Layer 2: update + max =================
    float m = -INFINITY;
    {
        #pragma unroll
        for (int q = 0; q < 8; q++) vacc[q] = 0;
        const u64* W = g_Wp_up2 + h * 2;
        #pragma unroll 4
        for (int k2 = 0; k2 < 32; k2++) {
            ulonglong2 w = *reinterpret_cast<const ulonglong2*>(W + k2 * (DH * 2));
            const float* r0 = xsT + (2 * k2) * PITCH + coff;
            row_fma(vacc, r0, w.x);
            row_fma(vacc, r0 + PITCH, w.y);
        }
        #pragma unroll 4
        for (int k2 = 0; k2 < 64; k2++) {
            ulonglong2 w = *reinterpret_cast<const ulonglong2*>(W + (32 + k2) * (DH * 2));
            const float* r0 = PT + (2 * k2) * PITCH + coff;
            row_fma(vacc, r0, w.x);
            row_fma(vacc, r0 + PITCH, w.y);
        }
        float bu = bu2[h];
        u64 bup = f2_pack(bu, bu);
        #pragma unroll
        for (int q = 0; q < 8; q++) {
            float2 f = f2_unpack(f2_add(vacc[q], bup));
            m = fmaxf(m, fmaxf(f.x, f.y));
        }
        m = fmaxf(m, 0.f);   // relu-then-max == max-then-relu
    }

    // Combine halves' maxes, then out[b] = sum_h m[h]*Wv[h] + bv
    if (half == 1) mx[h] = m;
    __syncthreads();
    float contrib = 0.f;
    if (half == 0) contrib = fmaxf(m, mx[h]) * Wv[h];
    #pragma unroll
    for (int o = 16; o; o >>= 1)
        contrib += __shfl_xor_sync(0xffffffffu, contrib, o);
    if ((tid & 31) == 0) red[tid >> 5] = contrib;
    __syncthreads();
    if (tid == 0) {
        float s = bv[0];
        #pragma unroll
        for (int w = 0; w < 8; w++) s += red[w];   // warps 4-7 contribute 0
        out[b] = s;
    }
}

extern "C" void kernel_launch(void* const* d_in, const int* in_sizes, int n_in,
                              void* d_out, int out_size) {
    const float* x   = (const float*)d_in[0];
    // d_in[1] = ext_adj (structure folded into the agg epilogue)
    const float* Wm1 = (const float*)d_in[2];
    const float* bm1 = (const float*)d_in[3];
    const float* Wm2 = (const float*)d_in[4];
    const float* bm2 = (const float*)d_in[5];
    const float* Wu1 = (const float*)d_in[6];
    const float* bu1 = (const float*)d_in[7];
    const float* Wu2 = (const float*)d_in[8];
    const float* bu2 = (const float*)d_in[9];
    const float* Wv  = (const float*)d_in[10];
    const float* bv  = (const float*)d_in[11];

    prep_weights_kernel<<<148, 256>>>(Wm1, Wm2, Wu1, Wu2);
    msggraph_kernel<<<NB, 256>>>(x, bm1, bm2, bu1, bu2, Wv, bv, (float*)d_out);
}

// round 5
// speedup vs baseline: 1.0077x; 1.0077x over previous
#include <cuda_runtime.h>
#include <math.h>

#define NB  512
#define NN  32
#define DSA 64
#define DH  128
#define PITCH 36   // floats/row: 144B -> every row+64B offset stays 16B-aligned for LDS.128

typedef unsigned long long u64;

#define ABSM  0x7fffffff7fffffffULL

// ---------- f32x2 helpers ----------
__device__ __forceinline__ u64 f2_fma(u64 a, u64 b, u64 c) {
    u64 d; asm("fma.rn.f32x2 %0,%1,%2,%3;" : "=l"(d) : "l"(a), "l"(b), "l"(c)); return d;
}
__device__ __forceinline__ u64 f2_add(u64 a, u64 b) {
    u64 d; asm("add.rn.f32x2 %0,%1,%2;" : "=l"(d) : "l"(a), "l"(b)); return d;
}
__device__ __forceinline__ u64 f2_pack(float lo, float hi) {
    u64 d; asm("mov.b64 %0,{%1,%2};" : "=l"(d) : "f"(lo), "f"(hi)); return d;
}
__device__ __forceinline__ float2 f2_unpack(u64 a) {
    float2 r; asm("mov.b64 {%0,%1},%2;" : "=f"(r.x), "=f"(r.y) : "l"(a)); return r;
}

// Paired-k, pre-duplicated transposed weights:
//   g_Wp[((k>>1)*DH + h)*2 + (k&1)] = pack(W[h][k], W[h][k])
// -> one LDG.128 yields packed weights for two consecutive k.
__device__ u64 g_Wp_msg1[128 * DH];   // k<128
__device__ u64 g_Wp_msg2[256 * DH];   // k<256
__device__ u64 g_Wp_up1 [192 * DH];   // k<192
__device__ u64 g_Wp_up2 [192 * DH];

__global__ void prep_weights_kernel(const float* __restrict__ Wm1,
                                    const float* __restrict__ Wm2,
                                    const float* __restrict__ Wu1,
                                    const float* __restrict__ Wu2) {
    const int stride = gridDim.x * blockDim.x;
    const int t0 = blockIdx.x * blockDim.x + threadIdx.x;
    for (int i = t0; i < DH * 128; i += stride) {
        int h = i >> 7, k = i & 127;
        float w = Wm1[i];
        g_Wp_msg1[((k >> 1) * DH + h) * 2 + (k & 1)] = f2_pack(w, w);
    }
    for (int i = t0; i < DH * 256; i += stride) {
        int h = i >> 8, k = i & 255;
        float w = Wm2[i];
        g_Wp_msg2[((k >> 1) * DH + h) * 2 + (k & 1)] = f2_pack(w, w);
    }
    for (int i = t0; i < DH * 192; i += stride) {
        int h = i / 192, k = i % 192;
        int d = ((k >> 1) * DH + h) * 2 + (k & 1);
        float w1 = Wu1[i], w2 = Wu2[i];
        g_Wp_up1[d] = f2_pack(w1, w1);
        g_Wp_up2[d] = f2_pack(w2, w2);
    }
}

// acc[0..7] += row-pairs (16 floats at `row`) * w2 (broadcast packed weight)
__device__ __forceinline__ void row_fma(u64* acc, const float* row, u64 w2) {
    const ulonglong2* xr = reinterpret_cast<const ulonglong2*>(row);
    #pragma unroll
    for (int q = 0; q < 4; q++) {
        ulonglong2 p = xr[q];
        acc[2*q]   = f2_fma(p.x, w2, acc[2*q]);
        acc[2*q+1] = f2_fma(p.y, w2, acc[2*q+1]);
    }
}
// dual-accumulator variant (msg layers): loads the row once
__device__ __forceinline__ void row_fma2(u64* accA, u64* accB, const float* row,
                                         u64 wa, u64 wb) {
    const ulonglong2* xr = reinterpret_cast<const ulonglong2*>(row);
    #pragma unroll
    for (int q = 0; q < 4; q++) {
        ulonglong2 p = xr[q];
        accA[2*q]   = f2_fma(p.x, wa, accA[2*q]);
        accB[2*q]   = f2_fma(p.x, wb, accB[2*q]);
        accA[2*q+1] = f2_fma(p.y, wa, accA[2*q+1]);
        accB[2*q+1] = f2_fma(p.y, wb, accB[2*q+1]);
    }
}

__global__ void __launch_bounds__(256, 2)   // 128-reg cap: NO spills (R4 lesson)
msggraph_kernel(const float* __restrict__ x,
                const float* __restrict__ bm1,
                const float* __restrict__ bm2,
                const float* __restrict__ bu1,
                const float* __restrict__ bu2,
                const float* __restrict__ Wv,
                const float* __restrict__ bv,
                float* __restrict__ out)
{
    __shared__ __align__(16) float xsT[DSA * PITCH];   // [k][j]
    __shared__ __align__(16) float PT [DH  * PITCH];   // [k][i]: agg1 -> v1 -> agg2
    __shared__ u64   Aex[16 * DH];                     // A exchange: [j2][h]
    __shared__ float mx[DH];
    __shared__ float red[8];

    const int tid  = threadIdx.x;
    const int h    = tid & 127;       // output channel
    const int half = tid >> 7;        // j/i half: 0 -> 0..15, 1 -> 16..31
    const int b    = blockIdx.x;
    const int coff = half * 16;       // column offset into shared rows

    // Load x[b] ([j=32][k=64] row-major) into transposed xsT[k][j].
    const float* xb = x + b * (NN * DSA);
    #pragma unroll
    for (int it = 0; it < (NN * DSA) / 256; it++) {
        int idx = it * 256 + tid;
        int j = idx >> 6, k = idx & 63;
        xsT[k * PITCH + j] = xb[idx];
    }
    __syncthreads();

    u64 accA[8], accB[8];   // my 16 j's as 8 packed pairs
    u64 Aall[16];           // all 32 A's (after exchange)
    u64 vacc[8];

    // ---- macro: msg epilogue (A-exchange + agg + PT write) ----
    // agg[i] = 0.5*(SA + 32*B_i + sum_j |A_j+B_i|) - relu(A_i+B_i)
#define MSG_EPILOGUE()                                                          \
    {                                                                           \
        _Pragma("unroll")                                                       \
        for (int q = 0; q < 8; q++) Aex[(half * 8 + q) * DH + h] = accA[q];     \
        __syncthreads();                                                        \
        _Pragma("unroll")                                                       \
        for (int q = 0; q < 8; q++) {                                           \
            Aall[half * 8 + q] = accA[q];                                       \
            Aall[(1 - half) * 8 + q] = Aex[((1 - half) * 8 + q) * DH + h];      \
        }                                                                       \
        u64 sAp = Aall[0];                                                      \
        _Pragma("unroll")                                                       \
        for (int j2 = 1; j2 < 16; j2++) sAp = f2_add(sAp, Aall[j2]);            \
        float2 sAf = f2_unpack(sAp);                                            \
        float SA = sAf.x + sAf.y;                                               \
        _Pragma("unroll")                                                       \
        for (int q = 0; q < 8; q++) {                                           \
            float2 B2 = f2_unpack(accB[q]);                                     \
            u64 bx = f2_pack(B2.x, B2.x), by = f2_pack(B2.y, B2.y);             \
            u64 ax = 0, ay = 0;                                                 \
            _Pragma("unroll")                                                   \
            for (int j2 = 0; j2 < 16; j2++) {                                   \
                u64 A = Aall[j2];                                               \
                ax = f2_add(ax, f2_add(A, bx) & ABSM);                          \
                ay = f2_add(ay, f2_add(A, by) & ABSM);                          \
            }                                                                   \
            float2 axf = f2_unpack(ax), ayf = f2_unpack(ay);                    \
            float2 Ai = f2_unpack(Aall[half * 8 + q]);                          \
            float gx = 0.5f * (fmaf(32.f, B2.x, SA) + axf.x + axf.y)            \
                       - fmaxf(Ai.x + B2.x, 0.f);                               \
            float gy = 0.5f * (fmaf(32.f, B2.y, SA) + ayf.x + ayf.y)            \
                       - fmaxf(Ai.y + B2.y, 0.f);                               \
            *reinterpret_cast<u64*>(&PT[h * PITCH + coff + 2 * q]) =            \
                f2_pack(gx, gy);                                                \
        }                                                                       \
    }

    // ================= Layer 1: msg =================
    {
        #pragma unroll
        for (int q = 0; q < 8; q++) { accA[q] = 0; accB[q] = 0; }
        const u64* W = g_Wp_msg1 + h * 2;
        #pragma unroll 4
        for (int k2 = 0; k2 < 32; k2++) {
            ulonglong2 wl = *reinterpret_cast<const ulonglong2*>(W + k2 * (DH * 2));
            ulonglong2 wr = *reinterpret_cast<const ulonglong2*>(W + (32 + k2) * (DH * 2));
            const float* r0 = xsT + (2 * k2) * PITCH + coff;
            row_fma2(accA, accB, r0, wl.x, wr.x);
            row_fma2(accA, accB, r0 + PITCH, wl.y, wr.y);
        }
        float bm = bm1[h];
        u64 bmp = f2_pack(bm, bm);
        #pragma unroll
        for (int q = 0; q < 8; q++) accA[q] = f2_add(accA[q], bmp);
        MSG_EPILOGUE()
    }
    __syncthreads();

    // ================= Layer 1: update =================
    {
        #pragma unroll
        for (int q = 0; q < 8; q++) vacc[q] = 0;
        const u64* W = g_Wp_up1 + h * 2;
        #pragma unroll 4
        for (int k2 = 0; k2 < 32; k2++) {            // x part (k<64)
            ulonglong2 w = *reinterpret_cast<const ulonglong2*>(W + k2 * (DH * 2));
            const float* r0 = xsT + (2 * k2) * PITCH + coff;
            row_fma(vacc, r0, w.x);
            row_fma(vacc, r0 + PITCH, w.y);
        }
        #pragma unroll 4
        for (int k2 = 0; k2 < 64; k2++) {            // agg part (k<128)
            ulonglong2 w = *reinterpret_cast<const ulonglong2*>(W + (32 + k2) * (DH * 2));
            const float* r0 = PT + (2 * k2) * PITCH + coff;
            row_fma(vacc, r0, w.x);
            row_fma(vacc, r0 + PITCH, w.y);
        }
        float bu = bu1[h];
        u64 bup = f2_pack(bu, bu);
        __syncthreads();   // everyone done reading PT(agg1)
        #pragma unroll
        for (int q = 0; q < 8; q++) {
            float2 t = f2_unpack(f2_add(vacc[q], bup));
            *reinterpret_cast<u64*>(&PT[h * PITCH + coff + 2 * q]) =
                f2_pack(fmaxf(t.x, 0.f), fmaxf(t.y, 0.f));
        }
    }
    __syncthreads();

    // ================= Layer 2: msg =================
    {
        #pragma unroll
        for (int q = 0; q < 8; q++) { accA[q] = 0; accB[q] = 0; }
        const u64* W = g_Wp_msg2 + h * 2;
        #pragma unroll 4
        for (int k2 = 0; k2 < 64; k2++) {
            ulonglong2 wl = *reinterpret_cast<const ulonglong2*>(W + k2 * (DH * 2));
            ulonglong2 wr = *reinterpret_cast<const ulonglong2*>(W + (64 + k2) * (DH * 2));
            const float* r0 = PT + (2 * k2) * PITCH + coff;
            row_fma2(accA, accB, r0, wl.x, wr.x);
            row_fma2(accA, accB, r0 + PITCH, wl.y, wr.y);
        }
        float bm = bm2[h];
        u64 bmp = f2_pack(bm, bm);
        #pragma unroll
        for (int q = 0; q < 8; q++) accA[q] = f2_add(accA[q], bmp);
        // the exchange's __syncthreads also separates GEMM reads of PT(v1)
        // from the epilogue's PT(agg2) writes
        MSG_EPILOGUE()
    }
    __syncthreads();

    // ================= Layer 2: update + max =================
    float m = -INFINITY;
    {
        #pragma unroll
        for (int q = 0; q < 8; q++) vacc[q] = 0;
        const u64* W = g_Wp_up2 + h * 2;
        #pragma unroll 4
        for (int k2 = 0; k2 < 32; k2++) {
            ulonglong2 w = *reinterpret_cast<const ulonglong2*>(W + k2 * (DH * 2));
            const float* r0 = xsT + (2 * k2) * PITCH + coff;
            row_fma(vacc, r0, w.x);
            row_fma(vacc, r0 + PITCH, w.y);
        }
        #pragma unroll 4
        for (int k2 = 0; k2 < 64; k2++) {
            ulonglong2 w = *reinterpret_cast<const ulonglong2*>(W + (32 + k2) * (DH * 2));
            const float* r0 = PT + (2 * k2) * PITCH + coff;
            row_fma(vacc, r0, w.x);
            row_fma(vacc, r0 + PITCH, w.y);
        }
        float bu = bu2[h];
        u64 bup = f2_pack(bu, bu);
        #pragma unroll
        for (int q = 0; q < 8; q++) {
            float2 f = f2_unpack(f2_add(vacc[q], bup));
            m = fmaxf(m, fmaxf(f.x, f.y));
        }
        m = fmaxf(m, 0.f);   // relu-then-max == max-then-relu
    }

    // Combine halves' maxes, then out[b] = sum_h m[h]*Wv[h] + bv
    if (half == 1) mx[h] = m;
    __syncthreads();
    float contrib = 0.f;
    if (half == 0) contrib = fmaxf(m, mx[h]) * Wv[h];
    #pragma unroll
    for (int o = 16; o; o >>= 1)
        contrib += __shfl_xor_sync(0xffffffffu, contrib, o);
    if ((tid & 31) == 0) red[tid >> 5] = contrib;
    __syncthreads();
    if (tid == 0) {
        float s = bv[0];
        #pragma unroll
        for (int w = 0; w < 8; w++) s += red[w];   // warps 4-7 contribute 0
        out[b] = s;
    }
}

extern "C" void kernel_launch(void* const* d_in, const int* in_sizes, int n_in,
                              void* d_out, int out_size) {
    const float* x   = (const float*)d_in[0];
    // d_in[1] = ext_adj (structure folded into the agg epilogue)
    const float* Wm1 = (const float*)d_in[2];
    const float* bm1 = (const float*)d_in[3];
    const float* Wm2 = (const float*)d_in[4];
    const float* bm2 = (const float*)d_in[5];
    const float* Wu1 = (const float*)d_in[6];
    const float* bu1 = (const float*)d_in[7];
    const float* Wu2 = (const float*)d_in[8];
    const float* bu2 = (const float*)d_in[9];
    const float* Wv  = (const float*)d_in[10];
    const float* bv  = (const float*)d_in[11];

    prep_weights_kernel<<<148, 256>>>(Wm1, Wm2, Wu1, Wu2);
    msggraph_kernel<<<NB, 256>>>(x, bm1, bm2, bu1, bu2, Wv, bv, (float*)d_out);
}

// round 6
// speedup vs baseline: 1.0620x; 1.0539x over previous
#include <cuda_runtime.h>
#include <math.h>

#define NB  512
#define NN  32
#define DSA 64
#define DH  128
#define PITCH 34   // floats/row, even -> 8B-aligned u64 pairs; 34%32=2 -> <=2-way on writes

typedef unsigned long long u64;
#define ABSM  0x7fffffff7fffffffULL

// ---------- f32x2 helpers ----------
__device__ __forceinline__ u64 f2_fma(u64 a, u64 b, u64 c) {
    u64 d; asm("fma.rn.f32x2 %0,%1,%2,%3;" : "=l"(d) : "l"(a), "l"(b), "l"(c)); return d;
}
__device__ __forceinline__ u64 f2_add(u64 a, u64 b) {
    u64 d; asm("add.rn.f32x2 %0,%1,%2;" : "=l"(d) : "l"(a), "l"(b)); return d;
}
__device__ __forceinline__ u64 f2_pack(float lo, float hi) {
    u64 d; asm("mov.b64 %0,{%1,%2};" : "=l"(d) : "f"(lo), "f"(hi)); return d;
}
__device__ __forceinline__ float2 f2_unpack(u64 a) {
    float2 r; asm("mov.b64 {%0,%1},%2;" : "=f"(r.x), "=f"(r.y) : "l"(a)); return r;
}

// Pre-duplicated transposed weights: g[k*DH + h] = pack(W[h][k], W[h][k]).
// Thread reads (h0,h1) adjacent -> one coalesced LDG.128 per k per operand.
__device__ u64 g_W2_msg1[128 * DH];
__device__ u64 g_W2_msg2[256 * DH];
__device__ u64 g_W2_up1 [192 * DH];
__device__ u64 g_W2_up2 [192 * DH];

__global__ void prep_weights_kernel(const float* __restrict__ Wm1,
                                    const float* __restrict__ Wm2,
                                    const float* __restrict__ Wu1,
                                    const float* __restrict__ Wu2) {
    const int stride = gridDim.x * blockDim.x;
    const int t0 = blockIdx.x * blockDim.x + threadIdx.x;
    for (int i = t0; i < DH * 128; i += stride) {
        int h = i >> 7, k = i & 127;
        float w = Wm1[i];
        g_W2_msg1[k * DH + h] = f2_pack(w, w);
    }
    for (int i = t0; i < DH * 256; i += stride) {
        int h = i >> 8, k = i & 255;
        float w = Wm2[i];
        g_W2_msg2[k * DH + h] = f2_pack(w, w);
    }
    for (int i = t0; i < DH * 192; i += stride) {
        int h = i / 192, k = i % 192;
        float w1 = Wu1[i], w2 = Wu2[i];
        g_W2_up1[k * DH + h] = f2_pack(w1, w1);
        g_W2_up2[k * DH + h] = f2_pack(w2, w2);
    }
}

__global__ void __launch_bounds__(128, 4)
msggraph_kernel(const float* __restrict__ x,
                const float* __restrict__ bm1,
                const float* __restrict__ bm2,
                const float* __restrict__ bu1,
                const float* __restrict__ bu2,
                const float* __restrict__ Wv,
                const float* __restrict__ bv,
                float* __restrict__ out)
{
    __shared__ __align__(16) float xsT[DSA * PITCH];  // [k][j]
    __shared__ __align__(16) float PT [DH  * PITCH];  // [k][i]: agg1 -> v1 -> agg2
    __shared__ __align__(16) u64   Aex[16 * DH];      // A exchange: [j2][h]
    __shared__ float mxs[2 * DH];
    __shared__ float red[4];

    const int tid  = threadIdx.x;
    const int hp   = tid & 63;     // h-pair index
    const int jh   = tid >> 6;     // j/i half
    const int h0   = hp * 2;
    const int h1   = h0 + 1;
    const int b    = blockIdx.x;
    const int coff = jh * 16;      // column offset in shared rows

    // Load x[b] ([j=32][k=64] row-major) into transposed xsT[k][j].
    const float* xb = x + b * (NN * DSA);
    #pragma unroll
    for (int it = 0; it < 16; it++) {
        int idx = it * 128 + tid;
        xsT[(idx & 63) * PITCH + (idx >> 6)] = xb[idx];
    }
    __syncthreads();

    u64 aA0[8], aA1[8], aB0[8], aB1[8];  // [h0/h1][local j-pair]
    u64 v0[8], v1[8];

    // ---- msg GEMM: A,B for both h's over this thread's 16 j's ----
#define MSG_GEMM(WB, NK, ACT)                                                 \
    {                                                                         \
        _Pragma("unroll")                                                     \
        for (int q = 0; q < 8; q++) { aA0[q]=0; aA1[q]=0; aB0[q]=0; aB1[q]=0; } \
        const u64* Wl = (WB) + h0;                                            \
        const u64* Wr = Wl + (NK) * DH;                                       \
        _Pragma("unroll 2")                                                   \
        for (int k = 0; k < (NK); k++) {                                      \
            ulonglong2 wl = *reinterpret_cast<const ulonglong2*>(Wl + k * DH);\
            ulonglong2 wr = *reinterpret_cast<const ulonglong2*>(Wr + k * DH);\
            const u64* ar = reinterpret_cast<const u64*>((ACT) + k * PITCH) + jh * 8; \
            _Pragma("unroll")                                                 \
            for (int q = 0; q < 8; q++) {                                     \
                u64 a = ar[q];                                                \
                aA0[q] = f2_fma(a, wl.x, aA0[q]);                             \
                aA1[q] = f2_fma(a, wl.y, aA1[q]);                             \
                aB0[q] = f2_fma(a, wr.x, aB0[q]);                             \
                aB1[q] = f2_fma(a, wr.y, aB1[q]);                             \
            }                                                                 \
        }                                                                     \
    }

    // ---- msg epilogue: bias, A-exchange, agg -> PT ----
    // agg[i] = 0.5*(SA + 32*B_i + sum_j |A_j+B_i|) - relu(A_i+B_i)
#define MSG_EPI(BM)                                                           \
    {                                                                         \
        float bb0 = (BM)[h0], bb1 = (BM)[h1];                                 \
        u64 bp0 = f2_pack(bb0, bb0), bp1 = f2_pack(bb1, bb1);                 \
        _Pragma("unroll")                                                     \
        for (int q = 0; q < 8; q++) {                                         \
            aA0[q] = f2_add(aA0[q], bp0);                                     \
            aA1[q] = f2_add(aA1[q], bp1);                                     \
            ulonglong2 st; st.x = aA0[q]; st.y = aA1[q];                      \
            *reinterpret_cast<ulonglong2*>(&Aex[(jh * 8 + q) * DH + h0]) = st;\
        }                                                                     \
        __syncthreads();                                                      \
        _Pragma("unroll")                                                     \
        for (int hs = 0; hs < 2; hs++) {                                      \
            const int h = h0 + hs;                                            \
            const u64* Bown = hs ? aB1 : aB0;                                 \
            u64 Aall[16];                                                     \
            _Pragma("unroll")                                                 \
            for (int j2 = 0; j2 < 16; j2++) Aall[j2] = Aex[j2 * DH + h];      \
            u64 sAp = Aall[0];                                                \
            _Pragma("unroll")                                                 \
            for (int j2 = 1; j2 < 16; j2++) sAp = f2_add(sAp, Aall[j2]);      \
            float2 sAf = f2_unpack(sAp);                                      \
            float SA = sAf.x + sAf.y;                                         \
            _Pragma("unroll")                                                 \
            for (int q = 0; q < 8; q++) {                                     \
                float2 B2 = f2_unpack(Bown[q]);                               \
                u64 bx = f2_pack(B2.x, B2.x), by = f2_pack(B2.y, B2.y);       \
                u64 ax = 0, ay = 0;                                           \
                _Pragma("unroll")                                             \
                for (int j2 = 0; j2 < 16; j2++) {                             \
                    u64 A = Aall[j2];                                         \
                    ax = f2_add(ax, f2_add(A, bx) & ABSM);                    \
                    ay = f2_add(ay, f2_add(A, by) & ABSM);                    \
                }                                                             \
                float2 axf = f2_unpack(ax), ayf = f2_unpack(ay);              \
                float2 Ai = f2_unpack(Aall[jh * 8 + q]);                      \
                float gx = 0.5f * (fmaf(32.f, B2.x, SA) + axf.x + axf.y)      \
                           - fmaxf(Ai.x + B2.x, 0.f);                         \
                float gy = 0.5f * (fmaf(32.f, B2.y, SA) + ayf.x + ayf.y)      \
                           - fmaxf(Ai.y + B2.y, 0.f);                         \
                *reinterpret_cast<u64*>(&PT[h * PITCH + coff + 2 * q]) =      \
                    f2_pack(gx, gy);                                          \
            }                                                                 \
        }                                                                     \
    }

    // ---- update GEMM: v for both h's over this thread's 16 i's ----
#define UP_GEMM(WB)                                                           \
    {                                                                         \
        _Pragma("unroll")                                                     \
        for (int q = 0; q < 8; q++) { v0[q] = 0; v1[q] = 0; }                 \
        const u64* Wu = (WB) + h0;                                            \
        _Pragma("unroll 2")                                                   \
        for (int k = 0; k < DSA; k++) {                                       \
            ulonglong2 w = *reinterpret_cast<const ulonglong2*>(Wu + k * DH); \
            const u64* ar = reinterpret_cast<const u64*>(xsT + k * PITCH) + jh * 8; \
            _Pragma("unroll")                                                 \
            for (int q = 0; q < 8; q++) {                                     \
                u64 a = ar[q];                                                \
                v0[q] = f2_fma(a, w.x, v0[q]);                                \
                v1[q] = f2_fma(a, w.y, v1[q]);                                \
            }                                                                 \
        }                                                                     \
        _Pragma("unroll 2")                                                   \
        for (int k = 0; k < DH; k++) {                                        \
            ulonglong2 w = *reinterpret_cast<const ulonglong2*>(Wu + (DSA + k) * DH); \
            const u64* ar = reinterpret_cast<const u64*>(PT + k * PITCH) + jh * 8;    \
            _Pragma("unroll")                                                 \
            for (int q = 0; q < 8; q++) {                                     \
                u64 a = ar[q];                                                \
                v0[q] = f2_fma(a, w.x, v0[q]);                                \
                v1[q] = f2_fma(a, w.y, v1[q]);                                \
            }                                                                 \
        }                                                                     \
    }

    // ================= Layer 1 =================
    MSG_GEMM(g_W2_msg1, DSA, xsT)
    MSG_EPI(bm1)
    __syncthreads();

    UP_GEMM(g_W2_up1)
    {
        float bb0 = bu1[h0], bb1 = bu1[h1];
        u64 bp0 = f2_pack(bb0, bb0), bp1 = f2_pack(bb1, bb1);
        __syncthreads();   // everyone done reading PT(agg1)
        #pragma unroll
        for (int q = 0; q < 8; q++) {
            float2 t0 = f2_unpack(f2_add(v0[q], bp0));
            float2 t1 = f2_unpack(f2_add(v1[q], bp1));
            *reinterpret_cast<u64*>(&PT[h0 * PITCH + coff + 2 * q]) =
                f2_pack(fmaxf(t0.x, 0.f), fmaxf(t0.y, 0.f));
            *reinterpret_cast<u64*>(&PT[h1 * PITCH + coff + 2 * q]) =
                f2_pack(fmaxf(t1.x, 0.f), fmaxf(t1.y, 0.f));
        }
    }
    __syncthreads();

    // ================= Layer 2 =================
    MSG_GEMM(g_W2_msg2, DH, PT)
    MSG_EPI(bm2)          // internal sync separates PT(v1) reads from agg2 writes
    __syncthreads();

    UP_GEMM(g_W2_up2)
    float mh0 = -INFINITY, mh1 = -INFINITY;
    {
        float bb0 = bu2[h0], bb1 = bu2[h1];
        u64 bp0 = f2_pack(bb0, bb0), bp1 = f2_pack(bb1, bb1);
        #pragma unroll
        for (int q = 0; q < 8; q++) {
            float2 t0 = f2_unpack(f2_add(v0[q], bp0));
            float2 t1 = f2_unpack(f2_add(v1[q], bp1));
            mh0 = fmaxf(mh0, fmaxf(t0.x, t0.y));
            mh1 = fmaxf(mh1, fmaxf(t1.x, t1.y));
        }
        mh0 = fmaxf(mh0, 0.f);   // relu-then-max == max-then-relu
        mh1 = fmaxf(mh1, 0.f);
    }
    mxs[jh * DH + h0] = mh0;
    mxs[jh * DH + h1] = mh1;
    __syncthreads();

    // out[b] = sum_h max-over-i(v2[i][h]) * Wv[h] + bv
    float m = fmaxf(mxs[tid], mxs[DH + tid]);
    float contrib = m * Wv[tid];
    #pragma unroll
    for (int o = 16; o; o >>= 1)
        contrib += __shfl_xor_sync(0xffffffffu, contrib, o);
    if ((tid & 31) == 0) red[tid >> 5] = contrib;
    __syncthreads();
    if (tid == 0) out[b] = red[0] + red[1] + red[2] + red[3] + bv[0];
}

extern "C" void kernel_launch(void* const* d_in, const int* in_sizes, int n_in,
                              void* d_out, int out_size) {
    const float* x   = (const float*)d_in[0];
    // d_in[1] = ext_adj (structure folded into the agg epilogue)
    const float* Wm1 = (const float*)d_in[2];
    const float* bm1 = (const float*)d_in[3];
    const float* Wm2 = (const float*)d_in[4];
    const float* bm2 = (const float*)d_in[5];
    const float* Wu1 = (const float*)d_in[6];
    const float* bu1 = (const float*)d_in[7];
    const float* Wu2 = (const float*)d_in[8];
    const float* bu2 = (const float*)d_in[9];
    const float* Wv  = (const float*)d_in[10];
    const float* bv  = (const float*)d_in[11];

    prep_weights_kernel<<<148, 256>>>(Wm1, Wm2, Wu1, Wu2);
    msggraph_kernel<<<NB, 128>>>(x, bm1, bm2, bu1, bu2, Wv, bv, (float*)d_out);
}